// round 13
// baseline (speedup 1.0000x reference)
#include <cuda_runtime.h>
#include <math.h>

#define BB   128
#define NN   1024
#define DIN  192
#define HH   128
#define KK   3
#define BN   (BB*NN)
#define NSUB 4
#define TOK  256
#define SCALE 0.08838834764831845f   // 1/sqrt(128)
#define LNEPS 1e-5f

// ------------------------- device scratch ------------------------------------
__device__ float g_inputsT[(size_t)BN * HH];     // 64 MB, [b][d][n]
__device__ float g_WpT[DIN * HH];
__device__ float g_WqT[HH * HH];
__device__ float g_WvT[HH * HH];
__device__ float g_WihT[HH * 3 * HH];
__device__ float g_WhhT[HH * 3 * HH];
__device__ float g_W1T[HH * 2 * HH];
__device__ float g_W2T[2 * HH * HH];
__device__ float g_slots[BB * KK * HH];
__device__ float g_qk[BB * KK * HH];
__device__ float g_qc[BB * KK];
__device__ float g_updp[BB * NSUB * KK * HH];
__device__ float g_sumwp[BB * NSUB * KK];

typedef unsigned long long u64;

__device__ __forceinline__ u64 pack2(float lo, float hi) {
    u64 r; asm("mov.b64 %0, {%1,%2};" : "=l"(r) : "f"(lo), "f"(hi)); return r;
}
__device__ __forceinline__ void unpack2(u64 v, float& lo, float& hi) {
    asm("mov.b64 {%0,%1}, %2;" : "=f"(lo), "=f"(hi) : "l"(v));
}
__device__ __forceinline__ u64 fma2(u64 a, u64 b, u64 c) {
    u64 d; asm("fma.rn.f32x2 %0, %1, %2, %3;" : "=l"(d) : "l"(a), "l"(b), "l"(c)); return d;
}
__device__ __forceinline__ float wred(float v) {
    #pragma unroll
    for (int o = 16; o; o >>= 1) v += __shfl_xor_sync(0xFFFFFFFFu, v, o);
    return v;
}
__device__ __forceinline__ float sigmoidf_(float x) { return 1.0f / (1.0f + expf(-x)); }
__device__ __forceinline__ float gelu_exact(float x) {
    return 0.5f * x * (1.0f + erff(x * 0.7071067811865476f));
}

// ------------------------- weight transposes ---------------------------------
__global__ void prep_transpose(const float* __restrict__ Wp, const float* __restrict__ Wq,
                               const float* __restrict__ Wv, const float* __restrict__ Wih,
                               const float* __restrict__ Whh, const float* __restrict__ W1,
                               const float* __restrict__ W2) {
    int i = blockIdx.x * blockDim.x + threadIdx.x;
    int stride = gridDim.x * blockDim.x;
    for (int t = i; t < HH * DIN; t += stride) { int j = t / DIN, e = t % DIN; g_WpT[e * HH + j] = Wp[t]; }
    for (int t = i; t < HH * HH; t += stride) { int j = t / HH, e = t % HH; g_WqT[e * HH + j] = Wq[t]; }
    for (int t = i; t < HH * HH; t += stride) { int d = t / HH, e = t % HH; g_WvT[e * HH + d] = Wv[t]; }
    for (int t = i; t < 3 * HH * HH; t += stride) { int o = t / HH, d = t % HH; g_WihT[d * (3 * HH) + o] = Wih[t]; }
    for (int t = i; t < 3 * HH * HH; t += stride) { int o = t / HH, d = t % HH; g_WhhT[d * (3 * HH) + o] = Whh[t]; }
    for (int t = i; t < 2 * HH * HH; t += stride) { int p = t / HH, d = t % HH; g_W1T[d * (2 * HH) + p] = W1[t]; }
    for (int t = i; t < 2 * HH * HH; t += stride) { int j = t / (2 * HH), p = t % (2 * HH); g_W2T[p * HH + j] = W2[t]; }
}

// ------------------------- init slots + LN + q + qk + c (iteration 0) --------
// 512 threads: all tid<N guards here have N <= 512. OK.
__global__ __launch_bounds__(512) void init_lnq_kernel(const float* __restrict__ noise,
                                                       const float* __restrict__ smu,
                                                       const float* __restrict__ sls,
                                                       const float* __restrict__ gs,
                                                       const float* __restrict__ bs,
                                                       const float* __restrict__ bq,
                                                       const float* __restrict__ Wk,
                                                       const float* __restrict__ bk) {
    const int b = blockIdx.x;
    const int tid = threadIdx.x;
    const int wid = tid >> 5, lane = tid & 31;
    __shared__ float s_s[KK][HH];
    __shared__ float q_s[KK][HH];
    __shared__ float sl_s[KK * HH];
    __shared__ float part_s[4][KK][HH];
    __shared__ float red1[12], red2[12];

    if (tid < KK * HH) {
        float v = smu[tid] + expf(sls[tid]) * noise[b * KK * HH + tid];
        sl_s[tid] = v;
        g_slots[b * KK * HH + tid] = v;
        float a = wred(v), a2 = wred(v * v);
        if (lane == 0) { red1[wid] = a; red2[wid] = a2; }
    }
    __syncthreads();
    if (tid < KK * HH) {
        const int ka = tid >> 7, j = tid & 127;
        float mu = (red1[ka*4] + red1[ka*4+1] + red1[ka*4+2] + red1[ka*4+3]) * (1.0f / HH);
        float var = (red2[ka*4] + red2[ka*4+1] + red2[ka*4+2] + red2[ka*4+3]) * (1.0f / HH) - mu * mu;
        float rstd = rsqrtf(var + LNEPS);
        s_s[ka][j] = (sl_s[tid] - mu) * rstd * gs[j] + bs[j];
    }
    __syncthreads();
    {
        const int j = tid & 127, part = tid >> 7;
        const int e0 = part * 32;
        float a0 = 0.f, a1 = 0.f, a2 = 0.f;
        #pragma unroll 8
        for (int e = 0; e < 32; e++) {
            float wv = g_WqT[(e0 + e) * HH + j];
            a0 += s_s[0][e0 + e] * wv;
            a1 += s_s[1][e0 + e] * wv;
            a2 += s_s[2][e0 + e] * wv;
        }
        part_s[part][0][j] = a0; part_s[part][1][j] = a1; part_s[part][2][j] = a2;
    }
    __syncthreads();
    if (tid < KK * HH) {
        const int ka = tid >> 7, j = tid & 127;
        float s = bq[j];
        #pragma unroll
        for (int p = 0; p < 4; p++) s += part_s[p][ka][j];
        q_s[ka][j] = s;
    }
    __syncthreads();
    {
        const int j = tid & 127, part = tid >> 7;
        const int d0 = part * 32;
        float a0 = 0.f, a1 = 0.f, a2 = 0.f;
        #pragma unroll 8
        for (int d = 0; d < 32; d++) {
            float wv = Wk[(d0 + d) * HH + j];
            a0 += q_s[0][d0 + d] * wv;
            a1 += q_s[1][d0 + d] * wv;
            a2 += q_s[2][d0 + d] * wv;
        }
        part_s[part][0][j] = a0; part_s[part][1][j] = a1; part_s[part][2][j] = a2;
    }
    __syncthreads();
    if (tid < KK * HH) {
        const int ka = tid >> 7, j = tid & 127;
        float s = 0.f;
        #pragma unroll
        for (int p = 0; p < 4; p++) s += part_s[p][ka][j];
        g_qk[b * KK * HH + tid] = s * SCALE;
        float pr = wred(q_s[ka][j] * bk[j]);
        if (lane == 0) red1[wid] = pr;
    }
    __syncthreads();
    if (tid < KK)
        g_qc[b * KK + tid] = (red1[tid*4] + red1[tid*4+1] + red1[tid*4+2] + red1[tid*4+3]) * SCALE;
}

// ------------------------- fused projection + LayerNorm (f32x2) --------------
#define TM 64
#define KB 16
__global__ __launch_bounds__(256) void proj_ln_kernel(const float* __restrict__ X,
                                                      const float* __restrict__ bp,
                                                      const float* __restrict__ gin,
                                                      const float* __restrict__ bin) {
    __shared__ union {
        struct { float xs_t[KB][66]; float ws[KB][HH]; } a;
        float stage[TM][129];
    } u;
    const int row0 = blockIdx.x * TM;
    const int tid = threadIdx.x;
    const int w = tid >> 5;
    const int l = tid & 31;

    u64 acc[4][4];
    #pragma unroll
    for (int p = 0; p < 4; p++)
        #pragma unroll
        for (int c = 0; c < 4; c++) acc[p][c] = 0ull;

    const int ld_row = tid >> 2;
    const int ld_seg = tid & 3;

    for (int k0 = 0; k0 < DIN; k0 += KB) {
        float4 xv = *(const float4*)(&X[(size_t)(row0 + ld_row) * DIN + k0 + ld_seg * 4]);
        u.a.xs_t[ld_seg * 4 + 0][ld_row] = xv.x;
        u.a.xs_t[ld_seg * 4 + 1][ld_row] = xv.y;
        u.a.xs_t[ld_seg * 4 + 2][ld_row] = xv.z;
        u.a.xs_t[ld_seg * 4 + 3][ld_row] = xv.w;
        #pragma unroll
        for (int i = 0; i < 2; i++) {
            int lin = i * 256 + tid;
            int kk = lin >> 5, jj = lin & 31;
            *(float4*)(&u.a.ws[kk][jj * 4]) = *(const float4*)(&g_WpT[(k0 + kk) * HH + jj * 4]);
        }
        __syncthreads();
        #pragma unroll
        for (int kk = 0; kk < KB; kk++) {
            float4 b4 = *(const float4*)(&u.a.ws[kk][l * 4]);
            u64 bx = pack2(b4.x, b4.x);
            u64 by = pack2(b4.y, b4.y);
            u64 bz = pack2(b4.z, b4.z);
            u64 bw = pack2(b4.w, b4.w);
            #pragma unroll
            for (int p = 0; p < 4; p++) {
                u64 a = *(const u64*)(&u.a.xs_t[kk][w * 8 + p * 2]);
                acc[p][0] = fma2(a, bx, acc[p][0]);
                acc[p][1] = fma2(a, by, acc[p][1]);
                acc[p][2] = fma2(a, bz, acc[p][2]);
                acc[p][3] = fma2(a, bw, acc[p][3]);
            }
        }
        __syncthreads();
    }

    const float4 bias = *(const float4*)(&bp[l * 4]);
    const float4 g4   = *(const float4*)(&gin[l * 4]);
    const float4 b4n  = *(const float4*)(&bin[l * 4]);

    #pragma unroll
    for (int p = 0; p < 4; p++) {
        float r0[4], r1[4];
        unpack2(acc[p][0], r0[0], r1[0]);
        unpack2(acc[p][1], r0[1], r1[1]);
        unpack2(acc[p][2], r0[2], r1[2]);
        unpack2(acc[p][3], r0[3], r1[3]);
        #pragma unroll
        for (int half = 0; half < 2; half++) {
            float* r = half ? r1 : r0;
            r[0] += bias.x; r[1] += bias.y; r[2] += bias.z; r[3] += bias.w;
            float s  = r[0] + r[1] + r[2] + r[3];
            float s2 = r[0]*r[0] + r[1]*r[1] + r[2]*r[2] + r[3]*r[3];
            s = wred(s); s2 = wred(s2);
            float mu = s * (1.0f / HH);
            float var = s2 * (1.0f / HH) - mu * mu;
            float rstd = rsqrtf(var + LNEPS);
            int rloc = w * 8 + p * 2 + half;
            u.stage[rloc][l * 4 + 0] = (r[0] - mu) * rstd * g4.x + b4n.x;
            u.stage[rloc][l * 4 + 1] = (r[1] - mu) * rstd * g4.y + b4n.y;
            u.stage[rloc][l * 4 + 2] = (r[2] - mu) * rstd * g4.z + b4n.z;
            u.stage[rloc][l * 4 + 3] = (r[3] - mu) * rstd * g4.w + b4n.w;
        }
    }
    __syncthreads();

    // transposed write: g_inputsT[b][d][n]
    const int bb = row0 >> 10;
    const int nbase = row0 & 1023;
    #pragma unroll
    for (int it = 0; it < 8; it++) {
        int lin = it * 256 + tid;          // 0..2047 float4-units
        int d = lin >> 4;                  // 128 dims
        int seg = lin & 15;                // 16 float4 per dim (64 n)
        float4 v;
        v.x = u.stage[seg * 4 + 0][d];
        v.y = u.stage[seg * 4 + 1][d];
        v.z = u.stage[seg * 4 + 2][d];
        v.w = u.stage[seg * 4 + 3][d];
        *(float4*)(&g_inputsT[((size_t)bb * HH + d) * NN + nbase + seg * 4]) = v;
    }
}

// ------------------------- attention: two-pass, minimal smem -----------------
// grid = BB*NSUB (512), 256 threads.
__global__ __launch_bounds__(256) void attn_kernel(float* __restrict__ attn_out) {
    const int bx = blockIdx.x;
    const int b = bx >> 2, sub = bx & 3;
    const int n0 = sub * TOK;
    const int tid = threadIdx.x;
    const int wid = tid >> 5, lane = tid & 31;
    __shared__ __align__(16) float qk_s[KK * HH];
    __shared__ float c_s[KK];
    __shared__ __align__(16) float a_s[KK][TOK];
    __shared__ float wr_s[8][KK];
    __shared__ float f2_s[2][KK][HH];

    for (int i = tid; i < KK * HH; i += 256) qk_s[i] = g_qk[b * KK * HH + i];
    if (tid < KK) c_s[tid] = g_qc[b * KK + tid];
    __syncthreads();

    const float* xT = g_inputsT + (size_t)b * HH * NN + n0;

    // ---- Pass 1: logits per token (thread-local), softmax, attn write
    {
        const float* xc = xT + tid;
        float d0 = c_s[0], d1 = c_s[1], d2 = c_s[2];
        #pragma unroll 4
        for (int dd = 0; dd < HH; dd += 4) {
            float q00 = qk_s[0 * HH + dd], q01 = qk_s[0 * HH + dd + 1], q02 = qk_s[0 * HH + dd + 2], q03 = qk_s[0 * HH + dd + 3];
            float q10 = qk_s[1 * HH + dd], q11 = qk_s[1 * HH + dd + 1], q12 = qk_s[1 * HH + dd + 2], q13 = qk_s[1 * HH + dd + 3];
            float q20 = qk_s[2 * HH + dd], q21 = qk_s[2 * HH + dd + 1], q22 = qk_s[2 * HH + dd + 2], q23 = qk_s[2 * HH + dd + 3];
            float x0 = xc[(size_t)(dd + 0) * NN];
            float x1 = xc[(size_t)(dd + 1) * NN];
            float x2 = xc[(size_t)(dd + 2) * NN];
            float x3 = xc[(size_t)(dd + 3) * NN];
            d0 += x0 * q00 + x1 * q01 + x2 * q02 + x3 * q03;
            d1 += x0 * q10 + x1 * q11 + x2 * q12 + x3 * q13;
            d2 += x0 * q20 + x1 * q21 + x2 * q22 + x3 * q23;
        }
        float m = fmaxf(d0, fmaxf(d1, d2));
        float e0 = expf(d0 - m), e1 = expf(d1 - m), e2 = expf(d2 - m);
        float inv = 1.0f / (e0 + e1 + e2);
        float a0 = e0 * inv, a1 = e1 * inv, a2 = e2 * inv;
        a_s[0][tid] = a0; a_s[1][tid] = a1; a_s[2][tid] = a2;
        attn_out[(size_t)b * KK * NN + 0 * NN + n0 + tid] = a0;
        attn_out[(size_t)b * KK * NN + 1 * NN + n0 + tid] = a1;
        attn_out[(size_t)b * KK * NN + 2 * NN + n0 + tid] = a2;
        float w0 = wred(a0), w1 = wred(a1), w2 = wred(a2);
        if (lane == 0) { wr_s[wid][0] = w0; wr_s[wid][1] = w1; wr_s[wid][2] = w2; }
    }
    __syncthreads();
    if (tid < KK) {
        float s = 0.f;
        #pragma unroll
        for (int g = 0; g < 8; g++) s += wr_s[g][tid];
        g_sumwp[(b * NSUB + sub) * KK + tid] = s;
    }

    // ---- Pass 2: dim-major, re-read from L2/L1, a broadcast from smem
    {
        const int d = tid & 127, th = tid >> 7;
        const float* xr = xT + (size_t)d * NN + th * 128;
        const float* a0p = &a_s[0][th * 128];
        const float* a1p = &a_s[1][th * 128];
        const float* a2p = &a_s[2][th * 128];
        float f0 = 0.f, f1 = 0.f, f2v = 0.f;
        #pragma unroll 8
        for (int t = 0; t < 128; t++) {
            float x = xr[t];
            f0  += x * a0p[t];
            f1  += x * a1p[t];
            f2v += x * a2p[t];
        }
        f2_s[th][0][d] = f0; f2_s[th][1][d] = f1; f2_s[th][2][d] = f2v;
    }
    __syncthreads();
    // FIXED: strided combine (384 outputs, 256 threads)
    for (int i = tid; i < KK * HH; i += 256) {
        const int ka = i >> 7, d = i & 127;
        g_updp[(size_t)(b * NSUB + sub) * KK * HH + i] = f2_s[0][ka][d] + f2_s[1][ka][d];
    }
}

// ------------------------- post: fp32, grid BB, 1024 thr, next-iter qk tail --
__global__ __launch_bounds__(1024) void post_kernel(const float* __restrict__ bv,
                                                    const float* __restrict__ bih,
                                                    const float* __restrict__ bhh,
                                                    const float* __restrict__ gm,
                                                    const float* __restrict__ bm,
                                                    const float* __restrict__ b1,
                                                    const float* __restrict__ b2,
                                                    const float* __restrict__ gs,
                                                    const float* __restrict__ bs,
                                                    const float* __restrict__ bq,
                                                    const float* __restrict__ Wk,
                                                    const float* __restrict__ bk,
                                                    float* __restrict__ out_slots) {
    const int b = blockIdx.x;
    const int tid = threadIdx.x;
    const int wid = tid >> 5, lane = tid & 31;
    __shared__ float upd_s[KK][HH];          // reused as s_s in tail
    __shared__ float h_s[KK][HH];
    __shared__ float x_s[KK][HH];            // reused as q_s in tail
    __shared__ float gi_s[KK][3 * HH];
    __shared__ float gh_s[KK][3 * HH];
    __shared__ float hn_s[KK][HH];
    __shared__ float m_s[KK][HH];            // reused for new-slot stash
    __shared__ float t_s[KK][2 * HH];
    __shared__ float part_s[8][KK][2 * HH];  // 24 KB
    __shared__ float sw_s[KK];
    __shared__ float red1[12], red2[12];

    // ---- Phase 0: reduce NSUB partials
    if (tid < KK * HH) {
        float s = 0.f;
        #pragma unroll
        for (int sub = 0; sub < NSUB; sub++)
            s += g_updp[(size_t)(b * NSUB + sub) * KK * HH + tid];
        upd_s[0][tid] = s;
        h_s[0][tid] = g_slots[b * KK * HH + tid];
    }
    if (tid < KK) {
        float s = 0.f;
        #pragma unroll
        for (int sub = 0; sub < NSUB; sub++) s += g_sumwp[(b * NSUB + sub) * KK + tid];
        sw_s[tid] = s;
    }
    __syncthreads();

    // ---- Phase 1: x = upd @ Wv^T + sumw*bv (split-K8)
    {
        const int j = tid & 127, part = tid >> 7;
        const int e0 = part * 16;
        float a0 = 0.f, a1 = 0.f, a2 = 0.f;
        #pragma unroll
        for (int e = 0; e < 16; e++) {
            float wv = g_WvT[(e0 + e) * HH + j];
            a0 += upd_s[0][e0 + e] * wv;
            a1 += upd_s[1][e0 + e] * wv;
            a2 += upd_s[2][e0 + e] * wv;
        }
        part_s[part][0][j] = a0; part_s[part][1][j] = a1; part_s[part][2][j] = a2;
    }
    __syncthreads();
    if (tid < KK * HH) {
        const int ka = tid >> 7, j = tid & 127;
        float s = sw_s[ka] * bv[j];
        #pragma unroll
        for (int p = 0; p < 8; p++) s += part_s[p][ka][j];
        x_s[ka][j] = s;
    }
    __syncthreads();

    // ---- Phase 2: GRU gates
    if (tid < 768) {
        const int is_hh = tid >= 384;
        const int o = is_hh ? tid - 384 : tid;
        const float* W = is_hh ? g_WhhT : g_WihT;
        const float (*src)[HH] = is_hh ? h_s : x_s;
        float a0 = 0.f, a1 = 0.f, a2 = 0.f;
        #pragma unroll 4
        for (int d = 0; d < HH; d++) {
            float wv = W[d * 384 + o];
            a0 += src[0][d] * wv;
            a1 += src[1][d] * wv;
            a2 += src[2][d] * wv;
        }
        if (is_hh) {
            float bb = bhh[o];
            gh_s[0][o] = a0 + bb; gh_s[1][o] = a1 + bb; gh_s[2][o] = a2 + bb;
        } else {
            float bb = bih[o];
            gi_s[0][o] = a0 + bb; gi_s[1][o] = a1 + bb; gi_s[2][o] = a2 + bb;
        }
    }
    __syncthreads();

    // ---- Phase 3: gate combine + LN(gm, bm)
    if (tid < KK * HH) {
        const int ka = tid >> 7, j = tid & 127;
        float r = sigmoidf_(gi_s[ka][j]       + gh_s[ka][j]);
        float z = sigmoidf_(gi_s[ka][128 + j] + gh_s[ka][128 + j]);
        float nn = tanhf(gi_s[ka][256 + j] + r * gh_s[ka][256 + j]);
        float hnew = (1.0f - z) * nn + z * h_s[ka][j];
        hn_s[ka][j] = hnew;
        float a = wred(hnew), a2 = wred(hnew * hnew);
        if (lane == 0) { red1[wid] = a; red2[wid] = a2; }
    }
    __syncthreads();
    if (tid < KK * HH) {
        const int ka = tid >> 7, j = tid & 127;
        float mu = (red1[ka*4] + red1[ka*4+1] + red1[ka*4+2] + red1[ka*4+3]) * (1.0f / HH);
        float var = (red2[ka*4] + red2[ka*4+1] + red2[ka*4+2] + red2[ka*4+3]) * (1.0f / HH) - mu * mu;
        float rstd = rsqrtf(var + LNEPS);
        m_s[ka][j] = (hn_s[ka][j] - mu) * rstd * gm[j] + bm[j];
    }
    __syncthreads();

    // ---- Phase 4: W1 + gelu (split-K4, 256 cols)
    {
        const int p = tid & 255, part = tid >> 8;
        const int d0 = part * 32;
        float a0 = 0.f, a1 = 0.f, a2 = 0.f;
        #pragma unroll 8
        for (int d = 0; d < 32; d++) {
            float wv = g_W1T[(d0 + d) * (2 * HH) + p];
            a0 += m_s[0][d0 + d] * wv;
            a1 += m_s[1][d0 + d] * wv;
            a2 += m_s[2][d0 + d] * wv;
        }
        part_s[part][0][p] = a0; part_s[part][1][p] = a1; part_s[part][2][p] = a2;
    }
    __syncthreads();
    if (tid < KK * 2 * HH) {
        const int ka = tid >> 8, p = tid & 255;
        float s = b1[p];
        #pragma unroll
        for (int q = 0; q < 4; q++) s += part_s[q][ka][p];
        t_s[ka][p] = gelu_exact(s);
    }
    __syncthreads();

    // ---- Phase 5: W2 + residual (split-K8)
    {
        const int j = tid & 127, part = tid >> 7;
        const int p0 = part * 32;
        float a0 = 0.f, a1 = 0.f, a2 = 0.f;
        #pragma unroll 8
        for (int p = 0; p < 32; p++) {
            float wv = g_W2T[(p0 + p) * HH + j];
            a0 += t_s[0][p0 + p] * wv;
            a1 += t_s[1][p0 + p] * wv;
            a2 += t_s[2][p0 + p] * wv;
        }
        part_s[part][0][j] = a0; part_s[part][1][j] = a1; part_s[part][2][j] = a2;
    }
    __syncthreads();
    if (tid < KK * HH) {
        const int ka = tid >> 7, j = tid & 127;
        float o = hn_s[ka][j] + b2[j];
        #pragma unroll
        for (int p = 0; p < 8; p++) o += part_s[p][ka][j];
        int idx = b * KK * HH + tid;
        g_slots[idx] = o;
        out_slots[idx] = o;
        m_s[0][tid & 1023] = o;              // stash new slots (flat)
    }
    __syncthreads();

    // ================ TAIL: LN + q + qk + c for next iteration ================
    if (tid < KK * HH) {
        float v = m_s[0][tid];
        float a = wred(v), a2 = wred(v * v);
        if (lane == 0) { red1[wid] = a; red2[wid] = a2; }
    }
    __syncthreads();
    if (tid < KK * HH) {
        const int ka = tid >> 7, j = tid & 127;
        float mu = (red1[ka*4] + red1[ka*4+1] + red1[ka*4+2] + red1[ka*4+3]) * (1.0f / HH);
        float var = (red2[ka*4] + red2[ka*4+1] + red2[ka*4+2] + red2[ka*4+3]) * (1.0f / HH) - mu * mu;
        float rstd = rsqrtf(var + LNEPS);
        upd_s[0][tid] = (m_s[0][tid] - mu) * rstd * gs[j] + bs[j];   // s_s
    }
    __syncthreads();
    // q = s @ Wq^T + bq (split-K8)
    {
        const int j = tid & 127, part = tid >> 7;
        const int e0 = part * 16;
        float a0 = 0.f, a1 = 0.f, a2 = 0.f;
        #pragma unroll
        for (int e = 0; e < 16; e++) {
            float wv = g_WqT[(e0 + e) * HH + j];
            a0 += upd_s[0][0 * 128 + e0 + e] * wv;
            a1 += upd_s[0][1 * 128 + e0 + e] * wv;
            a2 += upd_s[0][2 * 128 + e0 + e] * wv;
        }
        part_s[part][0][j] = a0; part_s[part][1][j] = a1; part_s[part][2][j] = a2;
    }
    __syncthreads();
    if (tid < KK * HH) {
        const int ka = tid >> 7, j = tid & 127;
        float s = bq[j];
        #pragma unroll
        for (int p = 0; p < 8; p++) s += part_s[p][ka][j];
        x_s[ka][j] = s;                       // q
    }
    __syncthreads();
    // qk = SCALE * q @ Wk (split-K8)
    {
        const int j = tid & 127, part = tid >> 7;
        const int d0 = part * 16;
        float a0 = 0.f, a1 = 0.f, a2 = 0.f;
        #pragma unroll
        for (int d = 0; d < 16; d++) {
            float wv = Wk[(d0 + d) * HH + j];
            a0 += x_s[0][d0 + d] * wv;
            a1 += x_s[1][d0 + d] * wv;
            a2 += x_s[2][d0 + d] * wv;
        }
        part_s[part][0][j] = a0; part_s[part][1][j] = a1; part_s[part][2][j] = a2;
    }
    __syncthreads();
    if (tid < KK * HH) {
        const int ka = tid >> 7, j = tid & 127;
        float s = 0.f;
        #pragma unroll
        for (int p = 0; p < 8; p++) s += part_s[p][ka][j];
        g_qk[b * KK * HH + tid] = s * SCALE;
        float pr = wred(x_s[ka][j] * bk[j]);
        if (lane == 0) red1[wid] = pr;
    }
    __syncthreads();
    if (tid < KK)
        g_qc[b * KK + tid] = (red1[tid*4] + red1[tid*4+1] + red1[tid*4+2] + red1[tid*4+3]) * SCALE;
}

// ------------------------- launch --------------------------------------------
extern "C" void kernel_launch(void* const* d_in, const int* in_sizes, int n_in,
                              void* d_out, int out_size) {
    const float* X       = (const float*)d_in[0];
    const float* noise   = (const float*)d_in[1];
    const float* slot_mu = (const float*)d_in[2];
    const float* slot_ls = (const float*)d_in[3];
    const float* Wp  = (const float*)d_in[4];
    const float* bp  = (const float*)d_in[5];
    const float* gin = (const float*)d_in[6];
    const float* bin = (const float*)d_in[7];
    const float* Wq  = (const float*)d_in[8];
    const float* bq  = (const float*)d_in[9];
    const float* Wk  = (const float*)d_in[10];
    const float* bk  = (const float*)d_in[11];
    const float* Wv  = (const float*)d_in[12];
    const float* bv  = (const float*)d_in[13];
    const float* Wih = (const float*)d_in[14];
    const float* bih = (const float*)d_in[15];
    const float* Whh = (const float*)d_in[16];
    const float* bhh = (const float*)d_in[17];
    const float* gs  = (const float*)d_in[18];
    const float* bs  = (const float*)d_in[19];
    const float* W1  = (const float*)d_in[20];
    const float* b1  = (const float*)d_in[21];
    const float* W2  = (const float*)d_in[22];
    const float* b2  = (const float*)d_in[23];
    const float* gm  = (const float*)d_in[24];
    const float* bm  = (const float*)d_in[25];

    float* out_slots = (float*)d_out;
    float* out_attn  = (float*)d_out + BB * KK * HH;

    prep_transpose<<<192, 256>>>(Wp, Wq, Wv, Wih, Whh, W1, W2);
    init_lnq_kernel<<<BB, 512>>>(noise, slot_mu, slot_ls, gs, bs, bq, Wk, bk);
    proj_ln_kernel<<<BN / TM, 256>>>(X, bp, gin, bin);

    for (int it = 0; it < 3; it++) {
        attn_kernel<<<BB * NSUB, 256>>>(out_attn);
        post_kernel<<<BB, 1024>>>(bv, bih, bhh, gm, bm, b1, b2,
                                  gs, bs, bq, Wk, bk, out_slots);
    }
}

// round 15
// speedup vs baseline: 1.5820x; 1.5820x over previous
#include <cuda_runtime.h>
#include <math.h>

#define BB   128
#define NN   1024
#define DIN  192
#define HH   128
#define KK   3
#define BN   (BB*NN)
#define NSUB 4
#define TOK  256
#define SCALE 0.08838834764831845f   // 1/sqrt(128)
#define LNEPS 1e-5f

// ------------------------- device scratch ------------------------------------
__device__ float g_inputsT[(size_t)BN * HH];     // 64 MB, [b][d][n]
__device__ float g_WpT[DIN * HH];
__device__ float g_WqT[HH * HH];
__device__ float g_WvT[HH * HH];
__device__ float g_WihT[HH * 3 * HH];
__device__ float g_WhhT[HH * 3 * HH];
__device__ float g_W1T[HH * 2 * HH];
__device__ float g_W2T[2 * HH * HH];
__device__ float g_slots[BB * KK * HH];
__device__ float g_qk[BB * KK * HH];
__device__ float g_qc[BB * KK];
__device__ float g_updp[BB * NSUB * KK * HH];
__device__ float g_sumwp[BB * NSUB * KK];

typedef unsigned long long u64;

__device__ __forceinline__ u64 pack2(float lo, float hi) {
    u64 r; asm("mov.b64 %0, {%1,%2};" : "=l"(r) : "f"(lo), "f"(hi)); return r;
}
__device__ __forceinline__ void unpack2(u64 v, float& lo, float& hi) {
    asm("mov.b64 {%0,%1}, %2;" : "=f"(lo), "=f"(hi) : "l"(v));
}
__device__ __forceinline__ u64 fma2(u64 a, u64 b, u64 c) {
    u64 d; asm("fma.rn.f32x2 %0, %1, %2, %3;" : "=l"(d) : "l"(a), "l"(b), "l"(c)); return d;
}
__device__ __forceinline__ float wred(float v) {
    #pragma unroll
    for (int o = 16; o; o >>= 1) v += __shfl_xor_sync(0xFFFFFFFFu, v, o);
    return v;
}
__device__ __forceinline__ float sigmoidf_(float x) { return 1.0f / (1.0f + expf(-x)); }
__device__ __forceinline__ float gelu_exact(float x) {
    return 0.5f * x * (1.0f + erff(x * 0.7071067811865476f));
}

// ------------------------- weight transposes ---------------------------------
__global__ void prep_transpose(const float* __restrict__ Wp, const float* __restrict__ Wq,
                               const float* __restrict__ Wv, const float* __restrict__ Wih,
                               const float* __restrict__ Whh, const float* __restrict__ W1,
                               const float* __restrict__ W2) {
    int i = blockIdx.x * blockDim.x + threadIdx.x;
    int stride = gridDim.x * blockDim.x;
    for (int t = i; t < HH * DIN; t += stride) { int j = t / DIN, e = t % DIN; g_WpT[e * HH + j] = Wp[t]; }
    for (int t = i; t < HH * HH; t += stride) { int j = t / HH, e = t % HH; g_WqT[e * HH + j] = Wq[t]; }
    for (int t = i; t < HH * HH; t += stride) { int d = t / HH, e = t % HH; g_WvT[e * HH + d] = Wv[t]; }
    for (int t = i; t < 3 * HH * HH; t += stride) { int o = t / HH, d = t % HH; g_WihT[d * (3 * HH) + o] = Wih[t]; }
    for (int t = i; t < 3 * HH * HH; t += stride) { int o = t / HH, d = t % HH; g_WhhT[d * (3 * HH) + o] = Whh[t]; }
    for (int t = i; t < 2 * HH * HH; t += stride) { int p = t / HH, d = t % HH; g_W1T[d * (2 * HH) + p] = W1[t]; }
    for (int t = i; t < 2 * HH * HH; t += stride) { int j = t / (2 * HH), p = t % (2 * HH); g_W2T[p * HH + j] = W2[t]; }
}

// ------------------------- init slots + LN + q + qk + c (iteration 0) --------
__global__ __launch_bounds__(512) void init_lnq_kernel(const float* __restrict__ noise,
                                                       const float* __restrict__ smu,
                                                       const float* __restrict__ sls,
                                                       const float* __restrict__ gs,
                                                       const float* __restrict__ bs,
                                                       const float* __restrict__ bq,
                                                       const float* __restrict__ Wk,
                                                       const float* __restrict__ bk) {
    const int b = blockIdx.x;
    const int tid = threadIdx.x;
    const int wid = tid >> 5, lane = tid & 31;
    __shared__ float s_s[KK][HH];
    __shared__ float q_s[KK][HH];
    __shared__ float sl_s[KK * HH];
    __shared__ float part_s[4][KK][HH];
    __shared__ float red1[12], red2[12];

    if (tid < KK * HH) {
        float v = smu[tid] + expf(sls[tid]) * noise[b * KK * HH + tid];
        sl_s[tid] = v;
        g_slots[b * KK * HH + tid] = v;
        float a = wred(v), a2 = wred(v * v);
        if (lane == 0) { red1[wid] = a; red2[wid] = a2; }
    }
    __syncthreads();
    if (tid < KK * HH) {
        const int ka = tid >> 7, j = tid & 127;
        float mu = (red1[ka*4] + red1[ka*4+1] + red1[ka*4+2] + red1[ka*4+3]) * (1.0f / HH);
        float var = (red2[ka*4] + red2[ka*4+1] + red2[ka*4+2] + red2[ka*4+3]) * (1.0f / HH) - mu * mu;
        float rstd = rsqrtf(var + LNEPS);
        s_s[ka][j] = (sl_s[tid] - mu) * rstd * gs[j] + bs[j];
    }
    __syncthreads();
    {
        const int j = tid & 127, part = tid >> 7;
        const int e0 = part * 32;
        float a0 = 0.f, a1 = 0.f, a2 = 0.f;
        #pragma unroll 8
        for (int e = 0; e < 32; e++) {
            float wv = g_WqT[(e0 + e) * HH + j];
            a0 += s_s[0][e0 + e] * wv;
            a1 += s_s[1][e0 + e] * wv;
            a2 += s_s[2][e0 + e] * wv;
        }
        part_s[part][0][j] = a0; part_s[part][1][j] = a1; part_s[part][2][j] = a2;
    }
    __syncthreads();
    if (tid < KK * HH) {
        const int ka = tid >> 7, j = tid & 127;
        float s = bq[j];
        #pragma unroll
        for (int p = 0; p < 4; p++) s += part_s[p][ka][j];
        q_s[ka][j] = s;
    }
    __syncthreads();
    {
        const int j = tid & 127, part = tid >> 7;
        const int d0 = part * 32;
        float a0 = 0.f, a1 = 0.f, a2 = 0.f;
        #pragma unroll 8
        for (int d = 0; d < 32; d++) {
            float wv = Wk[(d0 + d) * HH + j];
            a0 += q_s[0][d0 + d] * wv;
            a1 += q_s[1][d0 + d] * wv;
            a2 += q_s[2][d0 + d] * wv;
        }
        part_s[part][0][j] = a0; part_s[part][1][j] = a1; part_s[part][2][j] = a2;
    }
    __syncthreads();
    if (tid < KK * HH) {
        const int ka = tid >> 7, j = tid & 127;
        float s = 0.f;
        #pragma unroll
        for (int p = 0; p < 4; p++) s += part_s[p][ka][j];
        g_qk[b * KK * HH + tid] = s * SCALE;
        float pr = wred(q_s[ka][j] * bk[j]);
        if (lane == 0) red1[wid] = pr;
    }
    __syncthreads();
    if (tid < KK)
        g_qc[b * KK + tid] = (red1[tid*4] + red1[tid*4+1] + red1[tid*4+2] + red1[tid*4+3]) * SCALE;
}

// ------------------------- fused projection + LayerNorm (f32x2) --------------
#define TM 64
#define KB 16
__global__ __launch_bounds__(256) void proj_ln_kernel(const float* __restrict__ X,
                                                      const float* __restrict__ bp,
                                                      const float* __restrict__ gin,
                                                      const float* __restrict__ bin) {
    __shared__ union {
        struct { float xs_t[KB][66]; float ws[KB][HH]; } a;
        float stage[TM][129];
    } u;
    const int row0 = blockIdx.x * TM;
    const int tid = threadIdx.x;
    const int w = tid >> 5;
    const int l = tid & 31;

    u64 acc[4][4];
    #pragma unroll
    for (int p = 0; p < 4; p++)
        #pragma unroll
        for (int c = 0; c < 4; c++) acc[p][c] = 0ull;

    const int ld_row = tid >> 2;
    const int ld_seg = tid & 3;

    for (int k0 = 0; k0 < DIN; k0 += KB) {
        float4 xv = *(const float4*)(&X[(size_t)(row0 + ld_row) * DIN + k0 + ld_seg * 4]);
        u.a.xs_t[ld_seg * 4 + 0][ld_row] = xv.x;
        u.a.xs_t[ld_seg * 4 + 1][ld_row] = xv.y;
        u.a.xs_t[ld_seg * 4 + 2][ld_row] = xv.z;
        u.a.xs_t[ld_seg * 4 + 3][ld_row] = xv.w;
        #pragma unroll
        for (int i = 0; i < 2; i++) {
            int lin = i * 256 + tid;
            int kk = lin >> 5, jj = lin & 31;
            *(float4*)(&u.a.ws[kk][jj * 4]) = *(const float4*)(&g_WpT[(k0 + kk) * HH + jj * 4]);
        }
        __syncthreads();
        #pragma unroll
        for (int kk = 0; kk < KB; kk++) {
            float4 b4 = *(const float4*)(&u.a.ws[kk][l * 4]);
            u64 bx = pack2(b4.x, b4.x);
            u64 by = pack2(b4.y, b4.y);
            u64 bz = pack2(b4.z, b4.z);
            u64 bw = pack2(b4.w, b4.w);
            #pragma unroll
            for (int p = 0; p < 4; p++) {
                u64 a = *(const u64*)(&u.a.xs_t[kk][w * 8 + p * 2]);
                acc[p][0] = fma2(a, bx, acc[p][0]);
                acc[p][1] = fma2(a, by, acc[p][1]);
                acc[p][2] = fma2(a, bz, acc[p][2]);
                acc[p][3] = fma2(a, bw, acc[p][3]);
            }
        }
        __syncthreads();
    }

    const float4 bias = *(const float4*)(&bp[l * 4]);
    const float4 g4   = *(const float4*)(&gin[l * 4]);
    const float4 b4n  = *(const float4*)(&bin[l * 4]);

    #pragma unroll
    for (int p = 0; p < 4; p++) {
        float r0[4], r1[4];
        unpack2(acc[p][0], r0[0], r1[0]);
        unpack2(acc[p][1], r0[1], r1[1]);
        unpack2(acc[p][2], r0[2], r1[2]);
        unpack2(acc[p][3], r0[3], r1[3]);
        #pragma unroll
        for (int half = 0; half < 2; half++) {
            float* r = half ? r1 : r0;
            r[0] += bias.x; r[1] += bias.y; r[2] += bias.z; r[3] += bias.w;
            float s  = r[0] + r[1] + r[2] + r[3];
            float s2 = r[0]*r[0] + r[1]*r[1] + r[2]*r[2] + r[3]*r[3];
            s = wred(s); s2 = wred(s2);
            float mu = s * (1.0f / HH);
            float var = s2 * (1.0f / HH) - mu * mu;
            float rstd = rsqrtf(var + LNEPS);
            int rloc = w * 8 + p * 2 + half;
            u.stage[rloc][l * 4 + 0] = (r[0] - mu) * rstd * g4.x + b4n.x;
            u.stage[rloc][l * 4 + 1] = (r[1] - mu) * rstd * g4.y + b4n.y;
            u.stage[rloc][l * 4 + 2] = (r[2] - mu) * rstd * g4.z + b4n.z;
            u.stage[rloc][l * 4 + 3] = (r[3] - mu) * rstd * g4.w + b4n.w;
        }
    }
    __syncthreads();

    // transposed write: g_inputsT[b][d][n]
    const int bb = row0 >> 10;
    const int nbase = row0 & 1023;
    #pragma unroll
    for (int it = 0; it < 8; it++) {
        int lin = it * 256 + tid;          // 0..2047 float4-units
        int d = lin >> 4;                  // 128 dims
        int seg = lin & 15;                // 16 float4 per dim (64 n)
        float4 v;
        v.x = u.stage[seg * 4 + 0][d];
        v.y = u.stage[seg * 4 + 1][d];
        v.z = u.stage[seg * 4 + 2][d];
        v.w = u.stage[seg * 4 + 3][d];
        *(float4*)(&g_inputsT[((size_t)bb * HH + d) * NN + nbase + seg * 4]) = v;
    }
}

// ------------------------- attention: two-pass ------------------------------
// grid = BB*NSUB (512), 256 threads.
// Pass 1: thread = token, coalesced column reads, thread-local softmax.
// Pass 2: warp owns 16 dims, lanes cover 256 tokens as 2x float4 (coalesced),
//         a cached in registers, 3 warp-reductions per dim.
__global__ __launch_bounds__(256) void attn_kernel(float* __restrict__ attn_out) {
    const int bx = blockIdx.x;
    const int b = bx >> 2, sub = bx & 3;
    const int n0 = sub * TOK;
    const int tid = threadIdx.x;
    const int wid = tid >> 5, lane = tid & 31;
    __shared__ __align__(16) float qk_s[KK * HH];
    __shared__ float c_s[KK];
    __shared__ __align__(16) float a_s[KK][TOK];
    __shared__ float wr_s[8][KK];

    for (int i = tid; i < KK * HH; i += 256) qk_s[i] = g_qk[b * KK * HH + i];
    if (tid < KK) c_s[tid] = g_qc[b * KK + tid];
    __syncthreads();

    const float* xT = g_inputsT + (size_t)b * HH * NN + n0;

    // ---- Pass 1: logits per token (thread-local), softmax, attn write
    {
        const float* xc = xT + tid;
        float d0 = c_s[0], d1 = c_s[1], d2 = c_s[2];
        #pragma unroll 4
        for (int dd = 0; dd < HH; dd += 4) {
            float q00 = qk_s[0 * HH + dd], q01 = qk_s[0 * HH + dd + 1], q02 = qk_s[0 * HH + dd + 2], q03 = qk_s[0 * HH + dd + 3];
            float q10 = qk_s[1 * HH + dd], q11 = qk_s[1 * HH + dd + 1], q12 = qk_s[1 * HH + dd + 2], q13 = qk_s[1 * HH + dd + 3];
            float q20 = qk_s[2 * HH + dd], q21 = qk_s[2 * HH + dd + 1], q22 = qk_s[2 * HH + dd + 2], q23 = qk_s[2 * HH + dd + 3];
            float x0 = xc[(size_t)(dd + 0) * NN];
            float x1 = xc[(size_t)(dd + 1) * NN];
            float x2 = xc[(size_t)(dd + 2) * NN];
            float x3 = xc[(size_t)(dd + 3) * NN];
            d0 += x0 * q00 + x1 * q01 + x2 * q02 + x3 * q03;
            d1 += x0 * q10 + x1 * q11 + x2 * q12 + x3 * q13;
            d2 += x0 * q20 + x1 * q21 + x2 * q22 + x3 * q23;
        }
        float m = fmaxf(d0, fmaxf(d1, d2));
        float e0 = expf(d0 - m), e1 = expf(d1 - m), e2 = expf(d2 - m);
        float inv = 1.0f / (e0 + e1 + e2);
        float a0 = e0 * inv, a1 = e1 * inv, a2 = e2 * inv;
        a_s[0][tid] = a0; a_s[1][tid] = a1; a_s[2][tid] = a2;
        attn_out[(size_t)b * KK * NN + 0 * NN + n0 + tid] = a0;
        attn_out[(size_t)b * KK * NN + 1 * NN + n0 + tid] = a1;
        attn_out[(size_t)b * KK * NN + 2 * NN + n0 + tid] = a2;
        float w0 = wred(a0), w1 = wred(a1), w2 = wred(a2);
        if (lane == 0) { wr_s[wid][0] = w0; wr_s[wid][1] = w1; wr_s[wid][2] = w2; }
    }
    __syncthreads();
    if (tid < KK) {
        float s = 0.f;
        #pragma unroll
        for (int g = 0; g < 8; g++) s += wr_s[g][tid];
        g_sumwp[(b * NSUB + sub) * KK + tid] = s;
    }

    // ---- Pass 2: warp = 16 dims, lanes = 256 tokens (2x float4, coalesced)
    {
        float* updp = g_updp + (size_t)(b * NSUB + sub) * KK * HH;
        const int l4 = lane * 4;
        float4 a00 = *(const float4*)(&a_s[0][l4]);
        float4 a01 = *(const float4*)(&a_s[0][l4 + 128]);
        float4 a10 = *(const float4*)(&a_s[1][l4]);
        float4 a11 = *(const float4*)(&a_s[1][l4 + 128]);
        float4 a20 = *(const float4*)(&a_s[2][l4]);
        float4 a21 = *(const float4*)(&a_s[2][l4 + 128]);
        #pragma unroll
        for (int dl = 0; dl < 16; dl++) {
            const int d = wid * 16 + dl;
            const float* xr = xT + (size_t)d * NN;
            float4 x0 = *(const float4*)(&xr[l4]);
            float4 x1 = *(const float4*)(&xr[l4 + 128]);
            float f0 = x0.x * a00.x + x0.y * a00.y + x0.z * a00.z + x0.w * a00.w
                     + x1.x * a01.x + x1.y * a01.y + x1.z * a01.z + x1.w * a01.w;
            float f1 = x0.x * a10.x + x0.y * a10.y + x0.z * a10.z + x0.w * a10.w
                     + x1.x * a11.x + x1.y * a11.y + x1.z * a11.z + x1.w * a11.w;
            float f2 = x0.x * a20.x + x0.y * a20.y + x0.z * a20.z + x0.w * a20.w
                     + x1.x * a21.x + x1.y * a21.y + x1.z * a21.z + x1.w * a21.w;
            f0 = wred(f0); f1 = wred(f1); f2 = wred(f2);
            if (lane == 0) {
                updp[0 * HH + d] = f0;
                updp[1 * HH + d] = f1;
                updp[2 * HH + d] = f2;
            }
        }
    }
}

// ------------------------- post: fp32, grid BB, 1024 thr, next-iter qk tail --
__global__ __launch_bounds__(1024) void post_kernel(const float* __restrict__ bv,
                                                    const float* __restrict__ bih,
                                                    const float* __restrict__ bhh,
                                                    const float* __restrict__ gm,
                                                    const float* __restrict__ bm,
                                                    const float* __restrict__ b1,
                                                    const float* __restrict__ b2,
                                                    const float* __restrict__ gs,
                                                    const float* __restrict__ bs,
                                                    const float* __restrict__ bq,
                                                    const float* __restrict__ Wk,
                                                    const float* __restrict__ bk,
                                                    float* __restrict__ out_slots) {
    const int b = blockIdx.x;
    const int tid = threadIdx.x;
    const int wid = tid >> 5, lane = tid & 31;
    __shared__ float upd_s[KK][HH];
    __shared__ float h_s[KK][HH];
    __shared__ float x_s[KK][HH];
    __shared__ float gi_s[KK][3 * HH];
    __shared__ float gh_s[KK][3 * HH];
    __shared__ float hn_s[KK][HH];
    __shared__ float m_s[KK][HH];
    __shared__ float t_s[KK][2 * HH];
    __shared__ float part_s[8][KK][2 * HH];
    __shared__ float sw_s[KK];
    __shared__ float red1[12], red2[12];

    // ---- Phase 0
    if (tid < KK * HH) {
        float s = 0.f;
        #pragma unroll
        for (int sub = 0; sub < NSUB; sub++)
            s += g_updp[(size_t)(b * NSUB + sub) * KK * HH + tid];
        upd_s[0][tid] = s;
        h_s[0][tid] = g_slots[b * KK * HH + tid];
    }
    if (tid < KK) {
        float s = 0.f;
        #pragma unroll
        for (int sub = 0; sub < NSUB; sub++) s += g_sumwp[(b * NSUB + sub) * KK + tid];
        sw_s[tid] = s;
    }
    __syncthreads();

    // ---- Phase 1: x = upd @ Wv^T + sumw*bv (split-K8)
    {
        const int j = tid & 127, part = tid >> 7;
        const int e0 = part * 16;
        float a0 = 0.f, a1 = 0.f, a2 = 0.f;
        #pragma unroll
        for (int e = 0; e < 16; e++) {
            float wv = g_WvT[(e0 + e) * HH + j];
            a0 += upd_s[0][e0 + e] * wv;
            a1 += upd_s[1][e0 + e] * wv;
            a2 += upd_s[2][e0 + e] * wv;
        }
        part_s[part][0][j] = a0; part_s[part][1][j] = a1; part_s[part][2][j] = a2;
    }
    __syncthreads();
    if (tid < KK * HH) {
        const int ka = tid >> 7, j = tid & 127;
        float s = sw_s[ka] * bv[j];
        #pragma unroll
        for (int p = 0; p < 8; p++) s += part_s[p][ka][j];
        x_s[ka][j] = s;
    }
    __syncthreads();

    // ---- Phase 2: GRU gates
    if (tid < 768) {
        const int is_hh = tid >= 384;
        const int o = is_hh ? tid - 384 : tid;
        const float* W = is_hh ? g_WhhT : g_WihT;
        const float (*src)[HH] = is_hh ? h_s : x_s;
        float a0 = 0.f, a1 = 0.f, a2 = 0.f;
        #pragma unroll 4
        for (int d = 0; d < HH; d++) {
            float wv = W[d * 384 + o];
            a0 += src[0][d] * wv;
            a1 += src[1][d] * wv;
            a2 += src[2][d] * wv;
        }
        if (is_hh) {
            float bb = bhh[o];
            gh_s[0][o] = a0 + bb; gh_s[1][o] = a1 + bb; gh_s[2][o] = a2 + bb;
        } else {
            float bb = bih[o];
            gi_s[0][o] = a0 + bb; gi_s[1][o] = a1 + bb; gi_s[2][o] = a2 + bb;
        }
    }
    __syncthreads();

    // ---- Phase 3: gate combine + LN(gm, bm)
    if (tid < KK * HH) {
        const int ka = tid >> 7, j = tid & 127;
        float r = sigmoidf_(gi_s[ka][j]       + gh_s[ka][j]);
        float z = sigmoidf_(gi_s[ka][128 + j] + gh_s[ka][128 + j]);
        float nn = tanhf(gi_s[ka][256 + j] + r * gh_s[ka][256 + j]);
        float hnew = (1.0f - z) * nn + z * h_s[ka][j];
        hn_s[ka][j] = hnew;
        float a = wred(hnew), a2 = wred(hnew * hnew);
        if (lane == 0) { red1[wid] = a; red2[wid] = a2; }
    }
    __syncthreads();
    if (tid < KK * HH) {
        const int ka = tid >> 7, j = tid & 127;
        float mu = (red1[ka*4] + red1[ka*4+1] + red1[ka*4+2] + red1[ka*4+3]) * (1.0f / HH);
        float var = (red2[ka*4] + red2[ka*4+1] + red2[ka*4+2] + red2[ka*4+3]) * (1.0f / HH) - mu * mu;
        float rstd = rsqrtf(var + LNEPS);
        m_s[ka][j] = (hn_s[ka][j] - mu) * rstd * gm[j] + bm[j];
    }
    __syncthreads();

    // ---- Phase 4: W1 + gelu (split-K4, 256 cols)
    {
        const int p = tid & 255, part = tid >> 8;
        const int d0 = part * 32;
        float a0 = 0.f, a1 = 0.f, a2 = 0.f;
        #pragma unroll 8
        for (int d = 0; d < 32; d++) {
            float wv = g_W1T[(d0 + d) * (2 * HH) + p];
            a0 += m_s[0][d0 + d] * wv;
            a1 += m_s[1][d0 + d] * wv;
            a2 += m_s[2][d0 + d] * wv;
        }
        part_s[part][0][p] = a0; part_s[part][1][p] = a1; part_s[part][2][p] = a2;
    }
    __syncthreads();
    if (tid < KK * 2 * HH) {
        const int ka = tid >> 8, p = tid & 255;
        float s = b1[p];
        #pragma unroll
        for (int q = 0; q < 4; q++) s += part_s[q][ka][p];
        t_s[ka][p] = gelu_exact(s);
    }
    __syncthreads();

    // ---- Phase 5: W2 + residual (split-K8)
    {
        const int j = tid & 127, part = tid >> 7;
        const int p0 = part * 32;
        float a0 = 0.f, a1 = 0.f, a2 = 0.f;
        #pragma unroll 8
        for (int p = 0; p < 32; p++) {
            float wv = g_W2T[(p0 + p) * HH + j];
            a0 += t_s[0][p0 + p] * wv;
            a1 += t_s[1][p0 + p] * wv;
            a2 += t_s[2][p0 + p] * wv;
        }
        part_s[part][0][j] = a0; part_s[part][1][j] = a1; part_s[part][2][j] = a2;
    }
    __syncthreads();
    if (tid < KK * HH) {
        const int ka = tid >> 7, j = tid & 127;
        float o = hn_s[ka][j] + b2[j];
        #pragma unroll
        for (int p = 0; p < 8; p++) o += part_s[p][ka][j];
        int idx = b * KK * HH + tid;
        g_slots[idx] = o;
        out_slots[idx] = o;
        m_s[0][tid & 1023] = o;
    }
    __syncthreads();

    // ================ TAIL: LN + q + qk + c for next iteration ================
    if (tid < KK * HH) {
        float v = m_s[0][tid];
        float a = wred(v), a2 = wred(v * v);
        if (lane == 0) { red1[wid] = a; red2[wid] = a2; }
    }
    __syncthreads();
    if (tid < KK * HH) {
        const int ka = tid >> 7, j = tid & 127;
        float mu = (red1[ka*4] + red1[ka*4+1] + red1[ka*4+2] + red1[ka*4+3]) * (1.0f / HH);
        float var = (red2[ka*4] + red2[ka*4+1] + red2[ka*4+2] + red2[ka*4+3]) * (1.0f / HH) - mu * mu;
        float rstd = rsqrtf(var + LNEPS);
        upd_s[0][tid] = (m_s[0][tid] - mu) * rstd * gs[j] + bs[j];
    }
    __syncthreads();
    // q = s @ Wq^T + bq (split-K8)
    {
        const int j = tid & 127, part = tid >> 7;
        const int e0 = part * 16;
        float a0 = 0.f, a1 = 0.f, a2 = 0.f;
        #pragma unroll
        for (int e = 0; e < 16; e++) {
            float wv = g_WqT[(e0 + e) * HH + j];
            a0 += upd_s[0][0 * 128 + e0 + e] * wv;
            a1 += upd_s[0][1 * 128 + e0 + e] * wv;
            a2 += upd_s[0][2 * 128 + e0 + e] * wv;
        }
        part_s[part][0][j] = a0; part_s[part][1][j] = a1; part_s[part][2][j] = a2;
    }
    __syncthreads();
    if (tid < KK * HH) {
        const int ka = tid >> 7, j = tid & 127;
        float s = bq[j];
        #pragma unroll
        for (int p = 0; p < 8; p++) s += part_s[p][ka][j];
        x_s[ka][j] = s;
    }
    __syncthreads();
    // qk = SCALE * q @ Wk (split-K8)
    {
        const int j = tid & 127, part = tid >> 7;
        const int d0 = part * 16;
        float a0 = 0.f, a1 = 0.f, a2 = 0.f;
        #pragma unroll
        for (int d = 0; d < 16; d++) {
            float wv = Wk[(d0 + d) * HH + j];
            a0 += x_s[0][d0 + d] * wv;
            a1 += x_s[1][d0 + d] * wv;
            a2 += x_s[2][d0 + d] * wv;
        }
        part_s[part][0][j] = a0; part_s[part][1][j] = a1; part_s[part][2][j] = a2;
    }
    __syncthreads();
    if (tid < KK * HH) {
        const int ka = tid >> 7, j = tid & 127;
        float s = 0.f;
        #pragma unroll
        for (int p = 0; p < 8; p++) s += part_s[p][ka][j];
        g_qk[b * KK * HH + tid] = s * SCALE;
        float pr = wred(x_s[ka][j] * bk[j]);
        if (lane == 0) red1[wid] = pr;
    }
    __syncthreads();
    if (tid < KK)
        g_qc[b * KK + tid] = (red1[tid*4] + red1[tid*4+1] + red1[tid*4+2] + red1[tid*4+3]) * SCALE;
}

// ------------------------- launch --------------------------------------------
extern "C" void kernel_launch(void* const* d_in, const int* in_sizes, int n_in,
                              void* d_out, int out_size) {
    const float* X       = (const float*)d_in[0];
    const float* noise   = (const float*)d_in[1];
    const float* slot_mu = (const float*)d_in[2];
    const float* slot_ls = (const float*)d_in[3];
    const float* Wp  = (const float*)d_in[4];
    const float* bp  = (const float*)d_in[5];
    const float* gin = (const float*)d_in[6];
    const float* bin = (const float*)d_in[7];
    const float* Wq  = (const float*)d_in[8];
    const float* bq  = (const float*)d_in[9];
    const float* Wk  = (const float*)d_in[10];
    const float* bk  = (const float*)d_in[11];
    const float* Wv  = (const float*)d_in[12];
    const float* bv  = (const float*)d_in[13];
    const float* Wih = (const float*)d_in[14];
    const float* bih = (const float*)d_in[15];
    const float* Whh = (const float*)d_in[16];
    const float* bhh = (const float*)d_in[17];
    const float* gs  = (const float*)d_in[18];
    const float* bs  = (const float*)d_in[19];
    const float* W1  = (const float*)d_in[20];
    const float* b1  = (const float*)d_in[21];
    const float* W2  = (const float*)d_in[22];
    const float* b2  = (const float*)d_in[23];
    const float* gm  = (const float*)d_in[24];
    const float* bm  = (const float*)d_in[25];

    float* out_slots = (float*)d_out;
    float* out_attn  = (float*)d_out + BB * KK * HH;

    prep_transpose<<<192, 256>>>(Wp, Wq, Wv, Wih, Whh, W1, W2);
    init_lnq_kernel<<<BB, 512>>>(noise, slot_mu, slot_ls, gs, bs, bq, Wk, bk);
    proj_ln_kernel<<<BN / TM, 256>>>(X, bp, gin, bin);

    for (int it = 0; it < 3; it++) {
        attn_kernel<<<BB * NSUB, 256>>>(out_attn);
        post_kernel<<<BB, 1024>>>(bv, bih, bhh, gm, bm, b1, b2,
                                  gs, bs, bq, Wk, bk, out_slots);
    }
}